// round 12
// baseline (speedup 1.0000x reference)
#include <cuda_runtime.h>
#include <cuda_bf16.h>
#include <cstdint>
#include <cstddef>

#define N_ROWS   65536
#define A_DIM    1024
#define C_CLS    1000
#define S_AUG    2
#define M_TOTAL  (N_ROWS + S_AUG * C_CLS)   /* 67536 */
#define M_TILES  528
#define M_PAD    (M_TILES * 128)            /* 67584 */
#define NPAD     1024
#define STAGES   3
#define STAGE_BYTES 49152                   /* A 16KB + B 32KB */
#define SMEM_DYN (STAGES * STAGE_BYTES)     /* 147456 */

// ---------------- persistent device scratch ----------------
__device__ int   g_cnt[C_CLS];
__device__ int   g_off[C_CLS];
__device__ int   g_wptr[C_CLS];
__device__ int   g_idx[N_ROWS];
__device__ int   g_lab[N_ROWS];
__device__ int   g_blockor[128];
__device__ int   g_done;
__device__ float g_loss;
__device__ __nv_bfloat16 g_feats[(size_t)M_PAD * A_DIM];   // [x ; aug ; zero-pad] bf16
__device__ __nv_bfloat16 g_w[(size_t)NPAD * A_DIM];        // fc_w padded, bf16
__device__ float g_bias[NPAD];                             // fc_b - ba, pad = -1e30

// ============ PTX helpers ============
__device__ __forceinline__ uint32_t smem_u32(const void* p) {
    uint32_t a;
    asm("{ .reg .u64 t; cvta.to.shared.u64 t, %1; cvt.u32.u64 %0, t; }" : "=r"(a) : "l"(p));
    return a;
}
#define CP_ASYNC16(dst, src) \
    asm volatile("cp.async.cg.shared.global [%0], [%1], 16;" :: "r"(dst), "l"(src) : "memory")
#define CP_COMMIT() asm volatile("cp.async.commit_group;" ::: "memory")
#define CP_WAIT1()  asm volatile("cp.async.wait_group 1;" ::: "memory")
#define CP_WAIT0()  asm volatile("cp.async.wait_group 0;" ::: "memory")
#define LDSM4(r0, r1, r2, r3, a) \
    asm volatile("ldmatrix.sync.aligned.m8n8.x4.shared.b16 {%0,%1,%2,%3}, [%4];" \
                 : "=r"(r0), "=r"(r1), "=r"(r2), "=r"(r3) : "r"(a))
#define MMA(acc, a, b0, b1) \
    asm volatile("mma.sync.aligned.m16n8k16.row.col.f32.bf16.bf16.f32 " \
                 "{%0,%1,%2,%3},{%4,%5,%6,%7},{%8,%9},{%0,%1,%2,%3};" \
                 : "+f"((acc)[0]), "+f"((acc)[1]), "+f"((acc)[2]), "+f"((acc)[3]) \
                 : "r"((a)[0]), "r"((a)[1]), "r"((a)[2]), "r"((a)[3]), \
                   "r"(b0), "r"(b1))

// ---------------- #0: convw + int64-detect + pad + bias + counter resets ----------------
__global__ void k_pre(const int* __restrict__ raw, const float* __restrict__ fc_w,
                      const float* __restrict__ fc_b, const float* __restrict__ ba) {
    int b   = blockIdx.x;
    int tid = threadIdx.x;
    if (b < 1024) {
        int idx = b * 256 + tid;                 // 4 floats each
        __nv_bfloat162 lo, hi;
        if (idx < (C_CLS * A_DIM) / 4) {
            float4 v = reinterpret_cast<const float4*>(fc_w)[idx];
            lo = __floats2bfloat162_rn(v.x, v.y);
            hi = __floats2bfloat162_rn(v.z, v.w);
        } else {
            lo = __floats2bfloat162_rn(0.f, 0.f); hi = lo;
        }
        reinterpret_cast<__nv_bfloat162*>(g_w)[(size_t)idx * 2]     = lo;
        reinterpret_cast<__nv_bfloat162*>(g_w)[(size_t)idx * 2 + 1] = hi;
    } else if (b < 1152) {
        int d = b - 1024;
        int i = d * 256 + tid;                   // i < 32768
        int nz = (raw[2 * i + 1] != 0) ? 1 : 0;
        int any = __syncthreads_or(nz);
        if (tid == 0) g_blockor[d] = any;        // overwrite: no reset needed
    } else if (b < 1344) {
        int j = (b - 1152) * 256 + tid;          // zero-pad tail rows
        if (j < (M_PAD - M_TOTAL) * A_DIM)
            g_feats[(size_t)M_TOTAL * A_DIM + j] = __float2bfloat16(0.f);
    } else {
        int i = (b - 1344) * 256 + tid;          // i < 1024
        g_bias[i] = (i < C_CLS) ? (fc_b[i] - ba[i]) : -1e30f;
        if (i < C_CLS) { g_cnt[i] = 0; g_wptr[i] = 0; }
        if (i == 0) { g_loss = 0.f; g_done = 0; }
    }
}

// ---------------- #1: labels (int64/int32 auto) + histogram ----------------
__global__ void k_labels_count(const int* __restrict__ raw) {
    int tid = threadIdx.x;
    int v   = (tid < 128) ? g_blockor[tid] : 0;
    int any = __syncthreads_or(v);               // any odd word nonzero => int32 buffer
    int i   = blockIdx.x * blockDim.x + tid;
    if (i < N_ROWS) {
        int lab = any ? raw[i] : raw[2 * i];
        g_lab[i] = lab;
        atomicAdd(&g_cnt[lab], 1);
    }
}

// ---------------- #2: exclusive scan of class counts ----------------
__global__ void k_scan() {
    __shared__ int sa[1024], sb[1024];
    int tid = threadIdx.x;
    int v = (tid < C_CLS) ? g_cnt[tid] : 0;
    sa[tid] = v; __syncthreads();
    int* src = sa; int* dst = sb;
    for (int o = 1; o < 1024; o <<= 1) {
        int t = src[tid];
        if (tid >= o) t += src[tid - o];
        dst[tid] = t; __syncthreads();
        int* tmp = src; src = dst; dst = tmp;
    }
    if (tid < C_CLS) g_off[tid] = src[tid] - v;
}

// ---------------- #3: scatter row indices per class ----------------
__global__ void k_scatter() {
    int i = blockIdx.x * blockDim.x + threadIdx.x;
    if (i < N_ROWS) {
        int lab = g_lab[i];
        int pos = atomicAdd(&g_wptr[lab], 1);
        g_idx[g_off[lab] + pos] = i;
    }
}

// ---------------- #4: per-class stats + aug build + x->bf16 (gather via g_idx) ----------------
__global__ void k_stats(const float* __restrict__ x,
                        const float* __restrict__ eps,
                        const float* __restrict__ cov_prior,
                        const float* __restrict__ ave_prior,
                        const float* __restrict__ amount_prior) {
    int c   = blockIdx.x;
    int tid = threadIdx.x;            // thread owns 4 contiguous cols
    int cnt = g_cnt[c];
    int off = g_off[c];
    float sum[4] = {0, 0, 0, 0}, sq[4] = {0, 0, 0, 0};
#pragma unroll 2
    for (int j = 0; j < cnt; ++j) {
        int r = g_idx[off + j];
        float4 v = *reinterpret_cast<const float4*>(x + (size_t)r * A_DIM + tid * 4);
        __nv_bfloat162 lo = __floats2bfloat162_rn(v.x, v.y);
        __nv_bfloat162 hi = __floats2bfloat162_rn(v.z, v.w);
        uint2 pk;
        pk.x = *reinterpret_cast<uint32_t*>(&lo);
        pk.y = *reinterpret_cast<uint32_t*>(&hi);
        *reinterpret_cast<uint2*>(&g_feats[(size_t)r * A_DIM + tid * 4]) = pk;
        sum[0] += v.x; sq[0] += v.x * v.x;
        sum[1] += v.y; sq[1] += v.y * v.y;
        sum[2] += v.z; sq[2] += v.z * v.z;
        sum[3] += v.w; sq[3] += v.w * v.w;
    }
    float cntf  = (float)cnt;
    float cnt_c = (cnt == 0) ? 1.f : cntf;
    float w     = cntf / (cntf + amount_prior[c] + 1e-10f);
#pragma unroll
    for (int t = 0; t < 4; ++t) {
        int a = tid * 4 + t;
        float ave = sum[t] / cnt_c;
        float var = sq[t] / cnt_c - ave * ave;
        var = fmaxf(var, 0.f);
        if (var == 0.f) var = 1e-10f;
        float ap   = ave_prior[(size_t)c * A_DIM + a];
        float addl = w * (1.f - w) * (ap - ave) * (ap - ave);
        float ncov = cov_prior[(size_t)c * A_DIM + a] * (1.f - w) + var * w + addl;
        float nave = ap * (1.f - w) + ave * w;
#pragma unroll
        for (int s = 0; s < S_AUG; ++s) {
            float e = eps[((size_t)s * C_CLS + c) * A_DIM + a];
            g_feats[(size_t)(N_ROWS + s * C_CLS + c) * A_DIM + a] =
                __float2bfloat16(nave + ncov * e);
        }
    }
}

// ---------------- #5: R6 GEMM (128x256, 512 thr, bf16/f32) + fused final write ----------------
__global__ void __launch_bounds__(512, 1) k_gemm_loss(float* __restrict__ out) {
    extern __shared__ __align__(1024) char dyns[];   // STAGES x (A 16KB | B 32KB)
    __shared__ float s_bias[1024];
    __shared__ float s_redm[4][128], s_redl[4][128];
    __shared__ float s_rowm[128], s_rowl[128], s_rowlab[128];
    __shared__ int   s_lab[128];

    const int tid  = threadIdx.x;
    const int lane = tid & 31;
    const int warp = tid >> 5;
    const int wm   = warp & 3;
    const int wn   = warp >> 2;
    const int m0   = blockIdx.x * 128;
    const uint32_t stg = smem_u32(dyns);

    for (int i = tid; i < 1024; i += 512) s_bias[i] = g_bias[i];
    if (tid < 128) {
        int gr  = m0 + tid;
        int lab = (gr < N_ROWS) ? g_lab[gr]
                : (gr < M_TOTAL) ? (gr - N_ROWS) % C_CLS : -1;
        s_lab[tid]    = lab;
        s_rowm[tid]   = -1e30f;
        s_rowl[tid]   = 0.f;
        s_rowlab[tid] = 0.f;
    }

    const __nv_bfloat16* arow = g_feats + (size_t)m0 * A_DIM;

    auto issue = [&](int g, int s) {
        int nt = g >> 4, kt = g & 15;
        uint32_t ab = stg + (uint32_t)s * STAGE_BYTES;
        const __nv_bfloat16* asrc = arow + kt * 64;
        const __nv_bfloat16* bsrc = g_w + (size_t)(nt << 8) * A_DIM + kt * 64;
#pragma unroll
        for (int i = 0; i < 2; ++i) {            // A: 1024 chunks of 16B
            int q   = tid + i * 512;
            int row = q >> 3, seg = q & 7;
            uint32_t off = (uint32_t)(row * 128 + ((seg * 16) ^ ((row & 7) << 4)));
            CP_ASYNC16(ab + off, asrc + row * A_DIM + seg * 8);
        }
#pragma unroll
        for (int i = 0; i < 4; ++i) {            // B: 2048 chunks of 16B
            int q   = tid + i * 512;
            int row = q >> 3, seg = q & 7;
            uint32_t off = (uint32_t)(16384 + row * 128 + ((seg * 16) ^ ((row & 7) << 4)));
            CP_ASYNC16(ab + off, bsrc + row * A_DIM + seg * 8);
        }
        CP_COMMIT();
    };

    const int      arow0  = wm * 32 + (lane & 15);
    const int      brow0  = wn * 64 + (lane & 15);
    const uint32_t coloff = (uint32_t)((lane >> 4) * 16);
    const uint32_t swm    = (uint32_t)((lane & 7) << 4);

    issue(0, 0);
    issue(1, 1);

    float acc[2][8][4];
    int sC = 0, sI = 2;

    for (int g = 0; g < 64; ++g) {
        if (g < 63) CP_WAIT1(); else CP_WAIT0();
        __syncthreads();
        if (g + 2 < 64) {
            issue(g + 2, sI);
            if (++sI == STAGES) sI = 0;
        }
        if ((g & 15) == 0) {
#pragma unroll
            for (int mm = 0; mm < 2; ++mm)
#pragma unroll
                for (int nn = 0; nn < 8; ++nn)
#pragma unroll
                    for (int j = 0; j < 4; ++j) acc[mm][nn][j] = 0.f;
        }
        const uint32_t ab = stg + (uint32_t)sC * STAGE_BYTES;
        const uint32_t bb = ab + 16384;
        if (++sC == STAGES) sC = 0;
#pragma unroll
        for (int ks = 0; ks < 4; ++ks) {
            const uint32_t colb = (uint32_t)(ks * 32) + coloff;
            uint32_t a0[4], a1[4];
            LDSM4(a0[0], a0[1], a0[2], a0[3],
                  ab + (uint32_t)(arow0 * 128) + (colb ^ swm));
            LDSM4(a1[0], a1[1], a1[2], a1[3],
                  ab + (uint32_t)((arow0 + 16) * 128) + (colb ^ swm));
#pragma unroll
            for (int p = 0; p < 4; ++p) {
                uint32_t b[4];
                LDSM4(b[0], b[1], b[2], b[3],
                      bb + (uint32_t)((brow0 + p * 16) * 128) + (colb ^ swm));
                MMA(acc[0][2 * p],     a0, b[0], b[2]);
                MMA(acc[0][2 * p + 1], a0, b[1], b[3]);
                MMA(acc[1][2 * p],     a1, b[0], b[2]);
                MMA(acc[1][2 * p + 1], a1, b[1], b[3]);
            }
        }

        if ((g & 15) == 15) {
            // ---- two-pass epilogue for n-tile (256 classes) ----
            const int n0 = (g >> 4) * 256;
#pragma unroll
            for (int mm = 0; mm < 2; ++mm)
#pragma unroll
                for (int nn = 0; nn < 8; ++nn) {
                    int colb = n0 + wn * 64 + nn * 8 + (lane & 3) * 2;
                    acc[mm][nn][0] += s_bias[colb];
                    acc[mm][nn][1] += s_bias[colb + 1];
                    acc[mm][nn][2] += s_bias[colb];
                    acc[mm][nn][3] += s_bias[colb + 1];
                }
#pragma unroll
            for (int mm = 0; mm < 2; ++mm)
#pragma unroll
                for (int half = 0; half < 2; ++half) {
                    float tm = -1e30f;
#pragma unroll
                    for (int nn = 0; nn < 8; ++nn) {
                        tm = fmaxf(tm, acc[mm][nn][half * 2]);
                        tm = fmaxf(tm, acc[mm][nn][half * 2 + 1]);
                    }
                    tm = fmaxf(tm, __shfl_xor_sync(0xffffffffu, tm, 1));
                    tm = fmaxf(tm, __shfl_xor_sync(0xffffffffu, tm, 2));
                    if ((lane & 3) == 0)
                        s_redm[wn][wm * 32 + mm * 16 + half * 8 + (lane >> 2)] = tm;
                }
            __syncthreads();
#pragma unroll
            for (int mm = 0; mm < 2; ++mm)
#pragma unroll
                for (int half = 0; half < 2; ++half) {
                    int   row  = wm * 32 + mm * 16 + half * 8 + (lane >> 2);
                    float mnew = fmaxf(fmaxf(s_rowm[row],
                                       fmaxf(s_redm[0][row], s_redm[1][row])),
                                       fmaxf(s_redm[2][row], s_redm[3][row]));
                    int   lab  = s_lab[row];
                    float se   = 0.f;
#pragma unroll
                    for (int nn = 0; nn < 8; ++nn)
#pragma unroll
                        for (int i = 0; i < 2; ++i) {
                            float v = acc[mm][nn][half * 2 + i];
                            se += __expf(v - mnew);
                            int gcol = n0 + wn * 64 + nn * 8 + (lane & 3) * 2 + i;
                            if (gcol == lab) s_rowlab[row] = v;
                        }
                    se += __shfl_xor_sync(0xffffffffu, se, 1);
                    se += __shfl_xor_sync(0xffffffffu, se, 2);
                    if ((lane & 3) == 0) s_redl[wn][row] = se;
                }
            __syncthreads();
            if (tid < 128) {
                float mold = s_rowm[tid];
                float mnew = fmaxf(fmaxf(mold,
                                   fmaxf(s_redm[0][tid], s_redm[1][tid])),
                                   fmaxf(s_redm[2][tid], s_redm[3][tid]));
                s_rowl[tid] = s_rowl[tid] * __expf(mold - mnew)
                            + s_redl[0][tid] + s_redl[1][tid]
                            + s_redl[2][tid] + s_redl[3][tid];
                s_rowm[tid] = mnew;
            }
            __syncthreads();
        }
    }

    // ---- per-row loss, block reduce, device accumulate + fused final write ----
    if (tid < 128) {
        int   gr = m0 + tid;
        float c  = 0.f;
        if (gr < M_TOTAL)
            c = s_rowm[tid] + logf(s_rowl[tid]) - s_rowlab[tid];
#pragma unroll
        for (int o = 16; o; o >>= 1) c += __shfl_xor_sync(0xffffffffu, c, o);
        if (lane == 0) {
            atomicAdd(&g_loss, c);
            __threadfence();              // order loss atomic before g_done increment
        }
    }
    __syncthreads();
    if (tid == 0) {
        int done = atomicAdd(&g_done, 1);
        if (done == M_TILES - 1) {
            float total = atomicAdd(&g_loss, 0.f);   // L2-coherent read
            out[0] = total / (float)M_TOTAL;
        }
    }
}

// ---------------- launch ----------------
extern "C" void kernel_launch(void* const* d_in, const int* in_sizes, int n_in,
                              void* d_out, int out_size) {
    const float* x            = (const float*)d_in[0];
    const float* eps          = (const float*)d_in[1];
    const float* fc_w         = (const float*)d_in[2];
    const float* fc_b         = (const float*)d_in[3];
    const float* ba           = (const float*)d_in[4];
    const float* cov_prior    = (const float*)d_in[5];
    const float* ave_prior    = (const float*)d_in[6];
    const float* amount_prior = (const float*)d_in[7];
    const int*   labels_raw   = (const int*)d_in[8];

    cudaFuncSetAttribute(k_gemm_loss,
                         cudaFuncAttributeMaxDynamicSharedMemorySize, SMEM_DYN);

    k_pre<<<1348, 256>>>(labels_raw, fc_w, fc_b, ba);                // #0
    k_labels_count<<<256, 256>>>(labels_raw);                        // #1
    k_scan<<<1, 1024>>>();                                           // #2
    k_scatter<<<256, 256>>>();                                       // #3
    k_stats<<<C_CLS, 256>>>(x, eps, cov_prior, ave_prior, amount_prior); // #4
    k_gemm_loss<<<M_TILES, 512, SMEM_DYN>>>((float*)d_out);          // #5
}

// round 13
// speedup vs baseline: 1.0164x; 1.0164x over previous
#include <cuda_runtime.h>
#include <cuda_bf16.h>
#include <cstdint>
#include <cstddef>

#define N_ROWS   65536
#define A_DIM    1024
#define C_CLS    1000
#define S_AUG    2
#define M_TOTAL  (N_ROWS + S_AUG * C_CLS)   /* 67536 */
#define M_TILES  528
#define M_PAD    (M_TILES * 128)            /* 67584 */
#define NPAD     1024
#define STAGES   3
#define STAGE_BYTES 49152                   /* A 16KB + B 32KB */
#define SMEM_DYN (STAGES * STAGE_BYTES)     /* 147456 */

// ---------------- persistent device scratch ----------------
__device__ int   g_cnt[C_CLS];
__device__ int   g_off[C_CLS];
__device__ int   g_wptr[C_CLS];
__device__ int   g_idx[N_ROWS];
__device__ int   g_lab[N_ROWS];
__device__ int   g_blockor[128];
__device__ float g_loss;
__device__ __nv_bfloat16 g_feats[(size_t)M_PAD * A_DIM];   // [x ; aug ; zero-pad] bf16
__device__ __nv_bfloat16 g_w[(size_t)NPAD * A_DIM];        // fc_w padded, bf16
__device__ float g_bias[NPAD];                             // fc_b - ba, pad = -1e30

// ============ PTX helpers ============
__device__ __forceinline__ uint32_t smem_u32(const void* p) {
    uint32_t a;
    asm("{ .reg .u64 t; cvta.to.shared.u64 t, %1; cvt.u32.u64 %0, t; }" : "=r"(a) : "l"(p));
    return a;
}
#define CP_ASYNC16(dst, src) \
    asm volatile("cp.async.cg.shared.global [%0], [%1], 16;" :: "r"(dst), "l"(src) : "memory")
#define CP_COMMIT() asm volatile("cp.async.commit_group;" ::: "memory")
#define CP_WAIT1()  asm volatile("cp.async.wait_group 1;" ::: "memory")
#define LDSM4(r0, r1, r2, r3, a) \
    asm volatile("ldmatrix.sync.aligned.m8n8.x4.shared.b16 {%0,%1,%2,%3}, [%4];" \
                 : "=r"(r0), "=r"(r1), "=r"(r2), "=r"(r3) : "r"(a))
#define MMA(acc, a, b0, b1) \
    asm volatile("mma.sync.aligned.m16n8k16.row.col.f32.bf16.bf16.f32 " \
                 "{%0,%1,%2,%3},{%4,%5,%6,%7},{%8,%9},{%0,%1,%2,%3};" \
                 : "+f"((acc)[0]), "+f"((acc)[1]), "+f"((acc)[2]), "+f"((acc)[3]) \
                 : "r"((a)[0]), "r"((a)[1]), "r"((a)[2]), "r"((a)[3]), \
                   "r"(b0), "r"(b1))

// ---------------- #0: fused convw + int64-detect + counter init (R4 form) ----------------
__global__ void k_pre(const int* __restrict__ raw, const float* __restrict__ fc_w) {
    int b   = blockIdx.x;
    int tid = threadIdx.x;
    if (b < 1024) {
        int idx = b * 256 + tid;                 // 4 floats each
        __nv_bfloat162 lo, hi;
        if (idx < (C_CLS * A_DIM) / 4) {
            float4 v = reinterpret_cast<const float4*>(fc_w)[idx];
            lo = __floats2bfloat162_rn(v.x, v.y);
            hi = __floats2bfloat162_rn(v.z, v.w);
        } else {
            lo = __floats2bfloat162_rn(0.f, 0.f); hi = lo;
        }
        reinterpret_cast<__nv_bfloat162*>(g_w)[(size_t)idx * 2]     = lo;
        reinterpret_cast<__nv_bfloat162*>(g_w)[(size_t)idx * 2 + 1] = hi;
    } else if (b < 1152) {
        int d = b - 1024;
        int i = d * 256 + tid;                   // i < 32768
        int nz = (raw[2 * i + 1] != 0) ? 1 : 0;
        int any = __syncthreads_or(nz);
        if (tid == 0) g_blockor[d] = any;        // overwrite: no reset needed
    } else {
        int i = (b - 1152) * 256 + tid;
        if (i < C_CLS) { g_cnt[i] = 0; g_wptr[i] = 0; }
        if (i == 0) g_loss = 0.f;
    }
}

// ---------------- #1: labels (int64/int32 auto) + histogram ----------------
__global__ void k_labels_count(const int* __restrict__ raw) {
    int tid = threadIdx.x;
    int v   = (tid < 128) ? g_blockor[tid] : 0;
    int any = __syncthreads_or(v);               // any odd word nonzero => int32 buffer
    int i   = blockIdx.x * blockDim.x + tid;
    if (i < N_ROWS) {
        int lab = any ? raw[i] : raw[2 * i];
        g_lab[i] = lab;
        atomicAdd(&g_cnt[lab], 1);
    }
}

// ---------------- #2: scan (block0) + bias (block1) ----------------
__global__ void k_scan_bias(const float* __restrict__ fc_b, const float* __restrict__ ba) {
    int tid = threadIdx.x;
    if (blockIdx.x == 1) {
        g_bias[tid] = (tid < C_CLS) ? (fc_b[tid] - ba[tid]) : -1e30f;
        return;
    }
    __shared__ int sa[1024], sb[1024];
    int v = (tid < C_CLS) ? g_cnt[tid] : 0;
    sa[tid] = v; __syncthreads();
    int* src = sa; int* dst = sb;
    for (int o = 1; o < 1024; o <<= 1) {
        int t = src[tid];
        if (tid >= o) t += src[tid - o];
        dst[tid] = t; __syncthreads();
        int* tmp = src; src = dst; dst = tmp;
    }
    if (tid < C_CLS) g_off[tid] = src[tid] - v;
}

// ---------------- #3: scatter (blocks<256) + zero-pad tail rows ----------------
__global__ void k_scatter_pad() {
    int b   = blockIdx.x;
    int tid = threadIdx.x;
    if (b < 256) {
        int i = b * 256 + tid;
        int lab = g_lab[i];
        int pos = atomicAdd(&g_wptr[lab], 1);
        g_idx[g_off[lab] + pos] = i;
    } else {
        int j = (b - 256) * 256 + tid;
        if (j < (M_PAD - M_TOTAL) * A_DIM)
            g_feats[(size_t)M_TOTAL * A_DIM + j] = __float2bfloat16(0.f);
    }
}

// ---------------- #4: per-class stats + aug build + x->bf16 (gather via g_idx) ----------------
__global__ void k_stats(const float* __restrict__ x,
                        const float* __restrict__ eps,
                        const float* __restrict__ cov_prior,
                        const float* __restrict__ ave_prior,
                        const float* __restrict__ amount_prior) {
    int c   = blockIdx.x;
    int tid = threadIdx.x;            // thread owns 4 contiguous cols
    int cnt = g_cnt[c];
    int off = g_off[c];
    float sum[4] = {0, 0, 0, 0}, sq[4] = {0, 0, 0, 0};
#pragma unroll 2
    for (int j = 0; j < cnt; ++j) {
        int r = g_idx[off + j];
        float4 v = *reinterpret_cast<const float4*>(x + (size_t)r * A_DIM + tid * 4);
        __nv_bfloat162 lo = __floats2bfloat162_rn(v.x, v.y);
        __nv_bfloat162 hi = __floats2bfloat162_rn(v.z, v.w);
        uint2 pk;
        pk.x = *reinterpret_cast<uint32_t*>(&lo);
        pk.y = *reinterpret_cast<uint32_t*>(&hi);
        *reinterpret_cast<uint2*>(&g_feats[(size_t)r * A_DIM + tid * 4]) = pk;
        sum[0] += v.x; sq[0] += v.x * v.x;
        sum[1] += v.y; sq[1] += v.y * v.y;
        sum[2] += v.z; sq[2] += v.z * v.z;
        sum[3] += v.w; sq[3] += v.w * v.w;
    }
    float cntf  = (float)cnt;
    float cnt_c = (cnt == 0) ? 1.f : cntf;
    float w     = cntf / (cntf + amount_prior[c] + 1e-10f);
#pragma unroll
    for (int t = 0; t < 4; ++t) {
        int a = tid * 4 + t;
        float ave = sum[t] / cnt_c;
        float var = sq[t] / cnt_c - ave * ave;
        var = fmaxf(var, 0.f);
        if (var == 0.f) var = 1e-10f;
        float ap   = ave_prior[(size_t)c * A_DIM + a];
        float addl = w * (1.f - w) * (ap - ave) * (ap - ave);
        float ncov = cov_prior[(size_t)c * A_DIM + a] * (1.f - w) + var * w + addl;
        float nave = ap * (1.f - w) + ave * w;
#pragma unroll
        for (int s = 0; s < S_AUG; ++s) {
            float e = eps[((size_t)s * C_CLS + c) * A_DIM + a];
            g_feats[(size_t)(N_ROWS + s * C_CLS + c) * A_DIM + a] =
                __float2bfloat16(nave + ncov * e);
        }
    }
}

// ---------------- #5: R6 GEMM verbatim (128x256, 512 thr, bf16/f32, two-pass epi) ----------------
__global__ void __launch_bounds__(512, 1) k_gemm_loss() {
    extern __shared__ __align__(1024) char dyns[];   // STAGES x (A 16KB | B 32KB)
    __shared__ float s_bias[1024];
    __shared__ float s_redm[4][128], s_redl[4][128];
    __shared__ float s_rowm[128], s_rowl[128], s_rowlab[128];
    __shared__ int   s_lab[128];

    const int tid  = threadIdx.x;
    const int lane = tid & 31;
    const int warp = tid >> 5;
    const int wm   = warp & 3;
    const int wn   = warp >> 2;
    const int m0   = blockIdx.x * 128;
    const uint32_t stg = smem_u32(dyns);

    for (int i = tid; i < 1024; i += 512) s_bias[i] = g_bias[i];
    if (tid < 128) {
        int gr  = m0 + tid;
        int lab = (gr < N_ROWS) ? g_lab[gr]
                : (gr < M_TOTAL) ? (gr - N_ROWS) % C_CLS : -1;
        s_lab[tid]    = lab;
        s_rowm[tid]   = -1e30f;
        s_rowl[tid]   = 0.f;
        s_rowlab[tid] = 0.f;
    }

    const __nv_bfloat16* arow = g_feats + (size_t)m0 * A_DIM;

    auto issue = [&](int g, int s) {
        int nt = g >> 4, kt = g & 15;
        uint32_t ab = stg + (uint32_t)s * STAGE_BYTES;
        const __nv_bfloat16* asrc = arow + kt * 64;
        const __nv_bfloat16* bsrc = g_w + (size_t)(nt << 8) * A_DIM + kt * 64;
#pragma unroll
        for (int i = 0; i < 2; ++i) {            // A: 1024 chunks of 16B
            int q   = tid + i * 512;
            int row = q >> 3, seg = q & 7;
            uint32_t off = (uint32_t)(row * 128 + ((seg * 16) ^ ((row & 7) << 4)));
            CP_ASYNC16(ab + off, asrc + row * A_DIM + seg * 8);
        }
#pragma unroll
        for (int i = 0; i < 4; ++i) {            // B: 2048 chunks of 16B
            int q   = tid + i * 512;
            int row = q >> 3, seg = q & 7;
            uint32_t off = (uint32_t)(16384 + row * 128 + ((seg * 16) ^ ((row & 7) << 4)));
            CP_ASYNC16(ab + off, bsrc + row * A_DIM + seg * 8);
        }
        CP_COMMIT();
    };

    const int      arow0  = wm * 32 + (lane & 15);
    const int      brow0  = wn * 64 + (lane & 15);
    const uint32_t coloff = (uint32_t)((lane >> 4) * 16);
    const uint32_t swm    = (uint32_t)((lane & 7) << 4);

    issue(0, 0);
    issue(1, 1);

    float acc[2][8][4];
    int sC = 0, sI = 2;

    for (int g = 0; g < 64; ++g) {
        CP_WAIT1();
        __syncthreads();
        if (g + 2 < 64) {
            issue(g + 2, sI);
            if (++sI == STAGES) sI = 0;
        } else {
            // empty commit group: with "all but the 1 most-recent group must be
            // complete" semantics, the unconditional WAIT1 above now guarantees
            // the final real group (chunk 63) has landed by g=63.
            CP_COMMIT();
        }
        if ((g & 15) == 0) {
#pragma unroll
            for (int mm = 0; mm < 2; ++mm)
#pragma unroll
                for (int nn = 0; nn < 8; ++nn)
#pragma unroll
                    for (int j = 0; j < 4; ++j) acc[mm][nn][j] = 0.f;
        }
        const uint32_t ab = stg + (uint32_t)sC * STAGE_BYTES;
        const uint32_t bb = ab + 16384;
        if (++sC == STAGES) sC = 0;
#pragma unroll
        for (int ks = 0; ks < 4; ++ks) {
            const uint32_t colb = (uint32_t)(ks * 32) + coloff;
            uint32_t a0[4], a1[4];
            LDSM4(a0[0], a0[1], a0[2], a0[3],
                  ab + (uint32_t)(arow0 * 128) + (colb ^ swm));
            LDSM4(a1[0], a1[1], a1[2], a1[3],
                  ab + (uint32_t)((arow0 + 16) * 128) + (colb ^ swm));
#pragma unroll
            for (int p = 0; p < 4; ++p) {
                uint32_t b[4];
                LDSM4(b[0], b[1], b[2], b[3],
                      bb + (uint32_t)((brow0 + p * 16) * 128) + (colb ^ swm));
                MMA(acc[0][2 * p],     a0, b[0], b[2]);
                MMA(acc[0][2 * p + 1], a0, b[1], b[3]);
                MMA(acc[1][2 * p],     a1, b[0], b[2]);
                MMA(acc[1][2 * p + 1], a1, b[1], b[3]);
            }
        }

        if ((g & 15) == 15) {
            // ---- two-pass epilogue for n-tile (256 classes) ----
            const int n0 = (g >> 4) * 256;
#pragma unroll
            for (int mm = 0; mm < 2; ++mm)
#pragma unroll
                for (int nn = 0; nn < 8; ++nn) {
                    int colb = n0 + wn * 64 + nn * 8 + (lane & 3) * 2;
                    acc[mm][nn][0] += s_bias[colb];
                    acc[mm][nn][1] += s_bias[colb + 1];
                    acc[mm][nn][2] += s_bias[colb];
                    acc[mm][nn][3] += s_bias[colb + 1];
                }
#pragma unroll
            for (int mm = 0; mm < 2; ++mm)
#pragma unroll
                for (int half = 0; half < 2; ++half) {
                    float tm = -1e30f;
#pragma unroll
                    for (int nn = 0; nn < 8; ++nn) {
                        tm = fmaxf(tm, acc[mm][nn][half * 2]);
                        tm = fmaxf(tm, acc[mm][nn][half * 2 + 1]);
                    }
                    tm = fmaxf(tm, __shfl_xor_sync(0xffffffffu, tm, 1));
                    tm = fmaxf(tm, __shfl_xor_sync(0xffffffffu, tm, 2));
                    if ((lane & 3) == 0)
                        s_redm[wn][wm * 32 + mm * 16 + half * 8 + (lane >> 2)] = tm;
                }
            __syncthreads();
#pragma unroll
            for (int mm = 0; mm < 2; ++mm)
#pragma unroll
                for (int half = 0; half < 2; ++half) {
                    int   row  = wm * 32 + mm * 16 + half * 8 + (lane >> 2);
                    float mnew = fmaxf(fmaxf(s_rowm[row],
                                       fmaxf(s_redm[0][row], s_redm[1][row])),
                                       fmaxf(s_redm[2][row], s_redm[3][row]));
                    int   lab  = s_lab[row];
                    float se   = 0.f;
#pragma unroll
                    for (int nn = 0; nn < 8; ++nn)
#pragma unroll
                        for (int i = 0; i < 2; ++i) {
                            float v = acc[mm][nn][half * 2 + i];
                            se += __expf(v - mnew);
                            int gcol = n0 + wn * 64 + nn * 8 + (lane & 3) * 2 + i;
                            if (gcol == lab) s_rowlab[row] = v;
                        }
                    se += __shfl_xor_sync(0xffffffffu, se, 1);
                    se += __shfl_xor_sync(0xffffffffu, se, 2);
                    if ((lane & 3) == 0) s_redl[wn][row] = se;
                }
            __syncthreads();
            if (tid < 128) {
                float mold = s_rowm[tid];
                float mnew = fmaxf(fmaxf(mold,
                                   fmaxf(s_redm[0][tid], s_redm[1][tid])),
                                   fmaxf(s_redm[2][tid], s_redm[3][tid]));
                s_rowl[tid] = s_rowl[tid] * __expf(mold - mnew)
                            + s_redl[0][tid] + s_redl[1][tid]
                            + s_redl[2][tid] + s_redl[3][tid];
                s_rowm[tid] = mnew;
            }
            __syncthreads();
        }
    }

    if (tid < 128) {
        int   gr = m0 + tid;
        float c  = 0.f;
        if (gr < M_TOTAL)
            c = s_rowm[tid] + logf(s_rowl[tid]) - s_rowlab[tid];
#pragma unroll
        for (int o = 16; o; o >>= 1) c += __shfl_xor_sync(0xffffffffu, c, o);
        if (lane == 0) atomicAdd(&g_loss, c);
    }
}

__global__ void k_final(float* out) {
    out[0] = g_loss / (float)M_TOTAL;
}

// ---------------- launch ----------------
extern "C" void kernel_launch(void* const* d_in, const int* in_sizes, int n_in,
                              void* d_out, int out_size) {
    const float* x            = (const float*)d_in[0];
    const float* eps          = (const float*)d_in[1];
    const float* fc_w         = (const float*)d_in[2];
    const float* fc_b         = (const float*)d_in[3];
    const float* ba           = (const float*)d_in[4];
    const float* cov_prior    = (const float*)d_in[5];
    const float* ave_prior    = (const float*)d_in[6];
    const float* amount_prior = (const float*)d_in[7];
    const int*   labels_raw   = (const int*)d_in[8];

    cudaFuncSetAttribute(k_gemm_loss,
                         cudaFuncAttributeMaxDynamicSharedMemorySize, SMEM_DYN);

    k_pre<<<1156, 256>>>(labels_raw, fc_w);                          // #0
    k_labels_count<<<256, 256>>>(labels_raw);                        // #1
    k_scan_bias<<<2, 1024>>>(fc_b, ba);                              // #2
    k_scatter_pad<<<448, 256>>>();                                   // #3
    k_stats<<<C_CLS, 256>>>(x, eps, cov_prior, ave_prior, amount_prior); // #4
    k_gemm_loss<<<M_TILES, 512, SMEM_DYN>>>();                       // #5
    k_final<<<1, 1>>>((float*)d_out);                                // #6
}

// round 14
// speedup vs baseline: 1.0229x; 1.0064x over previous
#include <cuda_runtime.h>
#include <cuda_bf16.h>
#include <cstdint>
#include <cstddef>

#define N_ROWS   65536
#define A_DIM    1024
#define C_CLS    1000
#define S_AUG    2
#define M_TOTAL  (N_ROWS + S_AUG * C_CLS)   /* 67536 */
#define M_TILES  528
#define M_PAD    (M_TILES * 128)            /* 67584 */
#define NPAD     1024
#define STAGES   3
#define STAGE_BYTES 49152                   /* A 16KB + B 32KB */
#define SMEM_DYN (STAGES * STAGE_BYTES)     /* 147456 */

// ---------------- persistent device scratch ----------------
__device__ int   g_cnt[C_CLS];
__device__ int   g_off[C_CLS];
__device__ int   g_wptr[C_CLS];
__device__ int   g_idx[N_ROWS];
__device__ int   g_lab[N_ROWS];
__device__ int   g_blockor[128];
__device__ float g_loss;
__device__ __nv_bfloat16 g_feats[(size_t)M_PAD * A_DIM];   // [x ; aug ; zero-pad] bf16
__device__ __nv_bfloat16 g_w[(size_t)NPAD * A_DIM];        // fc_w padded, bf16
__device__ float g_bias[NPAD];                             // fc_b - ba, pad = -1e30

// ============ PTX helpers ============
__device__ __forceinline__ uint32_t smem_u32(const void* p) {
    uint32_t a;
    asm("{ .reg .u64 t; cvta.to.shared.u64 t, %1; cvt.u32.u64 %0, t; }" : "=r"(a) : "l"(p));
    return a;
}
#define CP_ASYNC16(dst, src) \
    asm volatile("cp.async.cg.shared.global [%0], [%1], 16;" :: "r"(dst), "l"(src) : "memory")
#define CP_COMMIT() asm volatile("cp.async.commit_group;" ::: "memory")
#define CP_WAIT1()  asm volatile("cp.async.wait_group 1;" ::: "memory")
#define LDSM4(r0, r1, r2, r3, a) \
    asm volatile("ldmatrix.sync.aligned.m8n8.x4.shared.b16 {%0,%1,%2,%3}, [%4];" \
                 : "=r"(r0), "=r"(r1), "=r"(r2), "=r"(r3) : "r"(a))
#define MMA(acc, a, b0, b1) \
    asm volatile("mma.sync.aligned.m16n8k16.row.col.f32.bf16.bf16.f32 " \
                 "{%0,%1,%2,%3},{%4,%5,%6,%7},{%8,%9},{%0,%1,%2,%3};" \
                 : "+f"((acc)[0]), "+f"((acc)[1]), "+f"((acc)[2]), "+f"((acc)[3]) \
                 : "r"((a)[0]), "r"((a)[1]), "r"((a)[2]), "r"((a)[3]), \
                   "r"(b0), "r"(b1))

// ---------------- #0: fused convw + int64-detect + counter init ----------------
__global__ void k_pre(const int* __restrict__ raw, const float* __restrict__ fc_w) {
    int b   = blockIdx.x;
    int tid = threadIdx.x;
    if (b < 1024) {
        int idx = b * 256 + tid;                 // 4 floats each
        __nv_bfloat162 lo, hi;
        if (idx < (C_CLS * A_DIM) / 4) {
            float4 v = reinterpret_cast<const float4*>(fc_w)[idx];
            lo = __floats2bfloat162_rn(v.x, v.y);
            hi = __floats2bfloat162_rn(v.z, v.w);
        } else {
            lo = __floats2bfloat162_rn(0.f, 0.f); hi = lo;
        }
        reinterpret_cast<__nv_bfloat162*>(g_w)[(size_t)idx * 2]     = lo;
        reinterpret_cast<__nv_bfloat162*>(g_w)[(size_t)idx * 2 + 1] = hi;
    } else if (b < 1152) {
        int d = b - 1024;
        int i = d * 256 + tid;                   // i < 32768
        int nz = (raw[2 * i + 1] != 0) ? 1 : 0;
        int any = __syncthreads_or(nz);
        if (tid == 0) g_blockor[d] = any;        // overwrite: no reset needed
    } else {
        int i = (b - 1152) * 256 + tid;
        if (i < C_CLS) { g_cnt[i] = 0; g_wptr[i] = 0; }
        if (i == 0) g_loss = 0.f;
    }
}

// ---------------- #1: labels (int64/int32 auto) + histogram ----------------
__global__ void k_labels_count(const int* __restrict__ raw) {
    int tid = threadIdx.x;
    int v   = (tid < 128) ? g_blockor[tid] : 0;
    int any = __syncthreads_or(v);               // any odd word nonzero => int32 buffer
    int i   = blockIdx.x * blockDim.x + tid;
    if (i < N_ROWS) {
        int lab = any ? raw[i] : raw[2 * i];
        g_lab[i] = lab;
        atomicAdd(&g_cnt[lab], 1);
    }
}

// ---------------- #2: scan (block0) + bias (block1) ----------------
__global__ void k_scan_bias(const float* __restrict__ fc_b, const float* __restrict__ ba) {
    int tid = threadIdx.x;
    if (blockIdx.x == 1) {
        g_bias[tid] = (tid < C_CLS) ? (fc_b[tid] - ba[tid]) : -1e30f;
        return;
    }
    __shared__ int sa[1024], sb[1024];
    int v = (tid < C_CLS) ? g_cnt[tid] : 0;
    sa[tid] = v; __syncthreads();
    int* src = sa; int* dst = sb;
    for (int o = 1; o < 1024; o <<= 1) {
        int t = src[tid];
        if (tid >= o) t += src[tid - o];
        dst[tid] = t; __syncthreads();
        int* tmp = src; src = dst; dst = tmp;
    }
    if (tid < C_CLS) g_off[tid] = src[tid] - v;
}

// ---------------- #3: scatter (blocks<256) + zero-pad tail rows ----------------
__global__ void k_scatter_pad() {
    int b   = blockIdx.x;
    int tid = threadIdx.x;
    if (b < 256) {
        int i = b * 256 + tid;
        int lab = g_lab[i];
        int pos = atomicAdd(&g_wptr[lab], 1);
        g_idx[g_off[lab] + pos] = i;
    } else {
        int j = (b - 256) * 256 + tid;
        if (j < (M_PAD - M_TOTAL) * A_DIM)
            g_feats[(size_t)M_TOTAL * A_DIM + j] = __float2bfloat16(0.f);
    }
}

// ---------------- #4: per-class stats + aug build + x->bf16 (gather via g_idx) ----------------
__global__ void k_stats(const float* __restrict__ x,
                        const float* __restrict__ eps,
                        const float* __restrict__ cov_prior,
                        const float* __restrict__ ave_prior,
                        const float* __restrict__ amount_prior) {
    int c   = blockIdx.x;
    int tid = threadIdx.x;            // thread owns 4 contiguous cols
    int cnt = g_cnt[c];
    int off = g_off[c];
    float sum[4] = {0, 0, 0, 0}, sq[4] = {0, 0, 0, 0};
#pragma unroll 2
    for (int j = 0; j < cnt; ++j) {
        int r = g_idx[off + j];
        float4 v = *reinterpret_cast<const float4*>(x + (size_t)r * A_DIM + tid * 4);
        __nv_bfloat162 lo = __floats2bfloat162_rn(v.x, v.y);
        __nv_bfloat162 hi = __floats2bfloat162_rn(v.z, v.w);
        uint2 pk;
        pk.x = *reinterpret_cast<uint32_t*>(&lo);
        pk.y = *reinterpret_cast<uint32_t*>(&hi);
        *reinterpret_cast<uint2*>(&g_feats[(size_t)r * A_DIM + tid * 4]) = pk;
        sum[0] += v.x; sq[0] += v.x * v.x;
        sum[1] += v.y; sq[1] += v.y * v.y;
        sum[2] += v.z; sq[2] += v.z * v.z;
        sum[3] += v.w; sq[3] += v.w * v.w;
    }
    float cntf  = (float)cnt;
    float cnt_c = (cnt == 0) ? 1.f : cntf;
    float w     = cntf / (cntf + amount_prior[c] + 1e-10f);
#pragma unroll
    for (int t = 0; t < 4; ++t) {
        int a = tid * 4 + t;
        float ave = sum[t] / cnt_c;
        float var = sq[t] / cnt_c - ave * ave;
        var = fmaxf(var, 0.f);
        if (var == 0.f) var = 1e-10f;
        float ap   = ave_prior[(size_t)c * A_DIM + a];
        float addl = w * (1.f - w) * (ap - ave) * (ap - ave);
        float ncov = cov_prior[(size_t)c * A_DIM + a] * (1.f - w) + var * w + addl;
        float nave = ap * (1.f - w) + ave * w;
#pragma unroll
        for (int s = 0; s < S_AUG; ++s) {
            float e = eps[((size_t)s * C_CLS + c) * A_DIM + a];
            g_feats[(size_t)(N_ROWS + s * C_CLS + c) * A_DIM + a] =
                __float2bfloat16(nave + ncov * e);
        }
    }
}

// ---------------- #5: R6 GEMM byte-faithful (128x256, 512 thr, bf16/f32) ----------------
__global__ void __launch_bounds__(512, 1) k_gemm_loss() {
    extern __shared__ __align__(1024) char dyns[];   // STAGES x (A 16KB | B 32KB)
    __shared__ float s_bias[1024];
    __shared__ float s_redm[4][128], s_redl[4][128];
    __shared__ float s_rowm[128], s_rowl[128], s_rowlab[128];
    __shared__ int   s_lab[128];

    const int tid  = threadIdx.x;
    const int lane = tid & 31;
    const int warp = tid >> 5;
    const int wm   = warp & 3;
    const int wn   = warp >> 2;
    const int m0   = blockIdx.x * 128;
    const uint32_t stg = smem_u32(dyns);

    for (int i = tid; i < 1024; i += 512) s_bias[i] = g_bias[i];
    if (tid < 128) {
        int gr  = m0 + tid;
        int lab = (gr < N_ROWS) ? g_lab[gr]
                : (gr < M_TOTAL) ? (gr - N_ROWS) % C_CLS : -1;
        s_lab[tid]    = lab;
        s_rowm[tid]   = -1e30f;
        s_rowl[tid]   = 0.f;
        s_rowlab[tid] = 0.f;
    }

    const __nv_bfloat16* arow = g_feats + (size_t)m0 * A_DIM;

    auto issue = [&](int g, int s) {
        int nt = g >> 4, kt = g & 15;
        uint32_t ab = stg + (uint32_t)s * STAGE_BYTES;
        const __nv_bfloat16* asrc = arow + kt * 64;
        const __nv_bfloat16* bsrc = g_w + (size_t)(nt << 8) * A_DIM + kt * 64;
#pragma unroll
        for (int i = 0; i < 2; ++i) {            // A: 1024 chunks of 16B
            int q   = tid + i * 512;
            int row = q >> 3, seg = q & 7;
            uint32_t off = (uint32_t)(row * 128 + ((seg * 16) ^ ((row & 7) << 4)));
            CP_ASYNC16(ab + off, asrc + row * A_DIM + seg * 8);
        }
#pragma unroll
        for (int i = 0; i < 4; ++i) {            // B: 2048 chunks of 16B
            int q   = tid + i * 512;
            int row = q >> 3, seg = q & 7;
            uint32_t off = (uint32_t)(16384 + row * 128 + ((seg * 16) ^ ((row & 7) << 4)));
            CP_ASYNC16(ab + off, bsrc + row * A_DIM + seg * 8);
        }
        CP_COMMIT();
    };

    const int      arow0  = wm * 32 + (lane & 15);
    const int      brow0  = wn * 64 + (lane & 15);
    const uint32_t coloff = (uint32_t)((lane >> 4) * 16);
    const uint32_t swm    = (uint32_t)((lane & 7) << 4);

    issue(0, 0);
    issue(1, 1);

    float acc[2][8][4];
    int sC = 0, sI = 2;

    for (int g = 0; g < 64; ++g) {
        CP_WAIT1();
        __syncthreads();
        if (g + 2 < 64) {
            issue(g + 2, sI);
            if (++sI == STAGES) sI = 0;
        }
        if ((g & 15) == 0) {
#pragma unroll
            for (int mm = 0; mm < 2; ++mm)
#pragma unroll
                for (int nn = 0; nn < 8; ++nn)
#pragma unroll
                    for (int j = 0; j < 4; ++j) acc[mm][nn][j] = 0.f;
        }
        const uint32_t ab = stg + (uint32_t)sC * STAGE_BYTES;
        const uint32_t bb = ab + 16384;
        if (++sC == STAGES) sC = 0;
#pragma unroll
        for (int ks = 0; ks < 4; ++ks) {
            const uint32_t colb = (uint32_t)(ks * 32) + coloff;
            uint32_t a0[4], a1[4];
            LDSM4(a0[0], a0[1], a0[2], a0[3],
                  ab + (uint32_t)(arow0 * 128) + (colb ^ swm));
            LDSM4(a1[0], a1[1], a1[2], a1[3],
                  ab + (uint32_t)((arow0 + 16) * 128) + (colb ^ swm));
#pragma unroll
            for (int p = 0; p < 4; ++p) {
                uint32_t b[4];
                LDSM4(b[0], b[1], b[2], b[3],
                      bb + (uint32_t)((brow0 + p * 16) * 128) + (colb ^ swm));
                MMA(acc[0][2 * p],     a0, b[0], b[2]);
                MMA(acc[0][2 * p + 1], a0, b[1], b[3]);
                MMA(acc[1][2 * p],     a1, b[0], b[2]);
                MMA(acc[1][2 * p + 1], a1, b[1], b[3]);
            }
        }

        if ((g & 15) == 15) {
            // ---- two-pass epilogue for n-tile (256 classes) ----
            const int n0 = (g >> 4) * 256;
#pragma unroll
            for (int mm = 0; mm < 2; ++mm)
#pragma unroll
                for (int nn = 0; nn < 8; ++nn) {
                    int colb = n0 + wn * 64 + nn * 8 + (lane & 3) * 2;
                    acc[mm][nn][0] += s_bias[colb];
                    acc[mm][nn][1] += s_bias[colb + 1];
                    acc[mm][nn][2] += s_bias[colb];
                    acc[mm][nn][3] += s_bias[colb + 1];
                }
#pragma unroll
            for (int mm = 0; mm < 2; ++mm)
#pragma unroll
                for (int half = 0; half < 2; ++half) {
                    float tm = -1e30f;
#pragma unroll
                    for (int nn = 0; nn < 8; ++nn) {
                        tm = fmaxf(tm, acc[mm][nn][half * 2]);
                        tm = fmaxf(tm, acc[mm][nn][half * 2 + 1]);
                    }
                    tm = fmaxf(tm, __shfl_xor_sync(0xffffffffu, tm, 1));
                    tm = fmaxf(tm, __shfl_xor_sync(0xffffffffu, tm, 2));
                    if ((lane & 3) == 0)
                        s_redm[wn][wm * 32 + mm * 16 + half * 8 + (lane >> 2)] = tm;
                }
            __syncthreads();
#pragma unroll
            for (int mm = 0; mm < 2; ++mm)
#pragma unroll
                for (int half = 0; half < 2; ++half) {
                    int   row  = wm * 32 + mm * 16 + half * 8 + (lane >> 2);
                    float mnew = fmaxf(fmaxf(s_rowm[row],
                                       fmaxf(s_redm[0][row], s_redm[1][row])),
                                       fmaxf(s_redm[2][row], s_redm[3][row]));
                    int   lab  = s_lab[row];
                    float se   = 0.f;
#pragma unroll
                    for (int nn = 0; nn < 8; ++nn)
#pragma unroll
                        for (int i = 0; i < 2; ++i) {
                            float v = acc[mm][nn][half * 2 + i];
                            se += __expf(v - mnew);
                            int gcol = n0 + wn * 64 + nn * 8 + (lane & 3) * 2 + i;
                            if (gcol == lab) s_rowlab[row] = v;
                        }
                    se += __shfl_xor_sync(0xffffffffu, se, 1);
                    se += __shfl_xor_sync(0xffffffffu, se, 2);
                    if ((lane & 3) == 0) s_redl[wn][row] = se;
                }
            __syncthreads();
            if (tid < 128) {
                float mold = s_rowm[tid];
                float mnew = fmaxf(fmaxf(mold,
                                   fmaxf(s_redm[0][tid], s_redm[1][tid])),
                                   fmaxf(s_redm[2][tid], s_redm[3][tid]));
                s_rowl[tid] = s_rowl[tid] * __expf(mold - mnew)
                            + s_redl[0][tid] + s_redl[1][tid]
                            + s_redl[2][tid] + s_redl[3][tid];
                s_rowm[tid] = mnew;
            }
            __syncthreads();
        }
    }

    if (tid < 128) {
        int   gr = m0 + tid;
        float c  = 0.f;
        if (gr < M_TOTAL)
            c = s_rowm[tid] + logf(s_rowl[tid]) - s_rowlab[tid];
#pragma unroll
        for (int o = 16; o; o >>= 1) c += __shfl_xor_sync(0xffffffffu, c, o);
        if (lane == 0) atomicAdd(&g_loss, c);
    }
}

__global__ void k_final(float* out) {
    out[0] = g_loss / (float)M_TOTAL;
}

// ---------------- launch ----------------
extern "C" void kernel_launch(void* const* d_in, const int* in_sizes, int n_in,
                              void* d_out, int out_size) {
    const float* x            = (const float*)d_in[0];
    const float* eps          = (const float*)d_in[1];
    const float* fc_w         = (const float*)d_in[2];
    const float* fc_b         = (const float*)d_in[3];
    const float* ba           = (const float*)d_in[4];
    const float* cov_prior    = (const float*)d_in[5];
    const float* ave_prior    = (const float*)d_in[6];
    const float* amount_prior = (const float*)d_in[7];
    const int*   labels_raw   = (const int*)d_in[8];

    cudaFuncSetAttribute(k_gemm_loss,
                         cudaFuncAttributeMaxDynamicSharedMemorySize, SMEM_DYN);

    k_pre<<<1156, 256>>>(labels_raw, fc_w);                          // #0
    k_labels_count<<<256, 256>>>(labels_raw);                        // #1
    k_scan_bias<<<2, 1024>>>(fc_b, ba);                              // #2
    k_scatter_pad<<<448, 256>>>();                                   // #3
    k_stats<<<C_CLS, 256>>>(x, eps, cov_prior, ave_prior, amount_prior); // #4
    k_gemm_loss<<<M_TILES, 512, SMEM_DYN>>>();                       // #5
    k_final<<<1, 1>>>((float*)d_out);                                // #6
}

// round 15
// speedup vs baseline: 1.0539x; 1.0303x over previous
#include <cuda_runtime.h>
#include <cuda_bf16.h>
#include <cstdint>
#include <cstddef>

#define N_ROWS   65536
#define A_DIM    1024
#define C_CLS    1000
#define S_AUG    2
#define M_TOTAL  (N_ROWS + S_AUG * C_CLS)   /* 67536 */
#define M_TILES  528
#define M_PAD    (M_TILES * 128)            /* 67584 */
#define NPAD     1024
#define STAGES   3
#define STAGE_BYTES 32768                   /* A 16KB + B 16KB */
#define SMEM_DYN (STAGES * STAGE_BYTES)     /* 98304 */

// ---------------- persistent device scratch ----------------
__device__ int   g_cnt[C_CLS];
__device__ int   g_off[C_CLS];
__device__ int   g_wptr[C_CLS];
__device__ int   g_idx[N_ROWS];
__device__ int   g_lab[N_ROWS];
__device__ int   g_blockor[128];
__device__ float g_loss;
__device__ __nv_bfloat16 g_feats[(size_t)M_PAD * A_DIM];   // [x ; aug ; zero-pad] bf16
__device__ __nv_bfloat16 g_w[(size_t)NPAD * A_DIM];        // fc_w padded, bf16
__device__ float g_bias[NPAD];                             // fc_b - ba, pad = -1e30

// ============ PTX helpers ============
__device__ __forceinline__ uint32_t smem_u32(const void* p) {
    uint32_t a;
    asm("{ .reg .u64 t; cvta.to.shared.u64 t, %1; cvt.u32.u64 %0, t; }" : "=r"(a) : "l"(p));
    return a;
}
#define CP_ASYNC16(dst, src) \
    asm volatile("cp.async.cg.shared.global [%0], [%1], 16;" :: "r"(dst), "l"(src) : "memory")
#define CP_COMMIT() asm volatile("cp.async.commit_group;" ::: "memory")
#define CP_WAIT1()  asm volatile("cp.async.wait_group 1;" ::: "memory")
#define LDSM4(r0, r1, r2, r3, a) \
    asm volatile("ldmatrix.sync.aligned.m8n8.x4.shared.b16 {%0,%1,%2,%3}, [%4];" \
                 : "=r"(r0), "=r"(r1), "=r"(r2), "=r"(r3) : "r"(a))
#define MMA(acc, a, b0, b1) \
    asm volatile("mma.sync.aligned.m16n8k16.row.col.f32.bf16.bf16.f32 " \
                 "{%0,%1,%2,%3},{%4,%5,%6,%7},{%8,%9},{%0,%1,%2,%3};" \
                 : "+f"((acc)[0]), "+f"((acc)[1]), "+f"((acc)[2]), "+f"((acc)[3]) \
                 : "r"((a)[0]), "r"((a)[1]), "r"((a)[2]), "r"((a)[3]), \
                   "r"(b0), "r"(b1))

// ---------------- #0: fused convw + int64-detect + counter init ----------------
__global__ void k_pre(const int* __restrict__ raw, const float* __restrict__ fc_w) {
    int b   = blockIdx.x;
    int tid = threadIdx.x;
    if (b < 1024) {
        int idx = b * 256 + tid;                 // 4 floats each
        __nv_bfloat162 lo, hi;
        if (idx < (C_CLS * A_DIM) / 4) {
            float4 v = reinterpret_cast<const float4*>(fc_w)[idx];
            lo = __floats2bfloat162_rn(v.x, v.y);
            hi = __floats2bfloat162_rn(v.z, v.w);
        } else {
            lo = __floats2bfloat162_rn(0.f, 0.f); hi = lo;
        }
        reinterpret_cast<__nv_bfloat162*>(g_w)[(size_t)idx * 2]     = lo;
        reinterpret_cast<__nv_bfloat162*>(g_w)[(size_t)idx * 2 + 1] = hi;
    } else if (b < 1152) {
        int d = b - 1024;
        int i = d * 256 + tid;                   // i < 32768
        int nz = (raw[2 * i + 1] != 0) ? 1 : 0;
        int any = __syncthreads_or(nz);
        if (tid == 0) g_blockor[d] = any;        // overwrite: no reset needed
    } else {
        int i = (b - 1152) * 256 + tid;
        if (i < C_CLS) { g_cnt[i] = 0; g_wptr[i] = 0; }
        if (i == 0) g_loss = 0.f;
    }
}

// ---------------- #1: labels (int64/int32 auto) + histogram ----------------
__global__ void k_labels_count(const int* __restrict__ raw) {
    int tid = threadIdx.x;
    int v   = (tid < 128) ? g_blockor[tid] : 0;
    int any = __syncthreads_or(v);               // any odd word nonzero => int32 buffer
    int i   = blockIdx.x * blockDim.x + tid;
    if (i < N_ROWS) {
        int lab = any ? raw[i] : raw[2 * i];
        g_lab[i] = lab;
        atomicAdd(&g_cnt[lab], 1);
    }
}

// ---------------- #2: scan (block0) + bias (block1) ----------------
__global__ void k_scan_bias(const float* __restrict__ fc_b, const float* __restrict__ ba) {
    int tid = threadIdx.x;
    if (blockIdx.x == 1) {
        g_bias[tid] = (tid < C_CLS) ? (fc_b[tid] - ba[tid]) : -1e30f;
        return;
    }
    __shared__ int sa[1024], sb[1024];
    int v = (tid < C_CLS) ? g_cnt[tid] : 0;
    sa[tid] = v; __syncthreads();
    int* src = sa; int* dst = sb;
    for (int o = 1; o < 1024; o <<= 1) {
        int t = src[tid];
        if (tid >= o) t += src[tid - o];
        dst[tid] = t; __syncthreads();
        int* tmp = src; src = dst; dst = tmp;
    }
    if (tid < C_CLS) g_off[tid] = src[tid] - v;
}

// ---------------- #3: scatter (blocks<256) + zero-pad tail rows ----------------
__global__ void k_scatter_pad() {
    int b   = blockIdx.x;
    int tid = threadIdx.x;
    if (b < 256) {
        int i = b * 256 + tid;
        int lab = g_lab[i];
        int pos = atomicAdd(&g_wptr[lab], 1);
        g_idx[g_off[lab] + pos] = i;
    } else {
        int j = (b - 256) * 256 + tid;
        if (j < (M_PAD - M_TOTAL) * A_DIM)
            g_feats[(size_t)M_TOTAL * A_DIM + j] = __float2bfloat16(0.f);
    }
}

// ---------------- #4: per-class stats + aug build + x->bf16 (gather via g_idx) ----------------
__global__ void k_stats(const float* __restrict__ x,
                        const float* __restrict__ eps,
                        const float* __restrict__ cov_prior,
                        const float* __restrict__ ave_prior,
                        const float* __restrict__ amount_prior) {
    int c   = blockIdx.x;
    int tid = threadIdx.x;            // thread owns 4 contiguous cols
    int cnt = g_cnt[c];
    int off = g_off[c];
    float sum[4] = {0, 0, 0, 0}, sq[4] = {0, 0, 0, 0};
#pragma unroll 2
    for (int j = 0; j < cnt; ++j) {
        int r = g_idx[off + j];
        float4 v = *reinterpret_cast<const float4*>(x + (size_t)r * A_DIM + tid * 4);
        __nv_bfloat162 lo = __floats2bfloat162_rn(v.x, v.y);
        __nv_bfloat162 hi = __floats2bfloat162_rn(v.z, v.w);
        uint2 pk;
        pk.x = *reinterpret_cast<uint32_t*>(&lo);
        pk.y = *reinterpret_cast<uint32_t*>(&hi);
        *reinterpret_cast<uint2*>(&g_feats[(size_t)r * A_DIM + tid * 4]) = pk;
        sum[0] += v.x; sq[0] += v.x * v.x;
        sum[1] += v.y; sq[1] += v.y * v.y;
        sum[2] += v.z; sq[2] += v.z * v.z;
        sum[3] += v.w; sq[3] += v.w * v.w;
    }
    float cntf  = (float)cnt;
    float cnt_c = (cnt == 0) ? 1.f : cntf;
    float w     = cntf / (cntf + amount_prior[c] + 1e-10f);
#pragma unroll
    for (int t = 0; t < 4; ++t) {
        int a = tid * 4 + t;
        float ave = sum[t] / cnt_c;
        float var = sq[t] / cnt_c - ave * ave;
        var = fmaxf(var, 0.f);
        if (var == 0.f) var = 1e-10f;
        float ap   = ave_prior[(size_t)c * A_DIM + a];
        float addl = w * (1.f - w) * (ap - ave) * (ap - ave);
        float ncov = cov_prior[(size_t)c * A_DIM + a] * (1.f - w) + var * w + addl;
        float nave = ap * (1.f - w) + ave * w;
#pragma unroll
        for (int s = 0; s < S_AUG; ++s) {
            float e = eps[((size_t)s * C_CLS + c) * A_DIM + a];
            g_feats[(size_t)(N_ROWS + s * C_CLS + c) * A_DIM + a] =
                __float2bfloat16(nave + ncov * e);
        }
    }
}

// ---------------- #5: 128x128-tile pipelined HMMA GEMM + loss (R4 champion form) ----------------
__global__ void __launch_bounds__(256, 2) k_gemm_loss() {
    extern __shared__ __align__(1024) char dyns[];   // STAGES x (A 16KB | B 16KB)
    __shared__ float s_bias[1024];
    __shared__ float s_redm[2][128], s_redl[2][128];
    __shared__ float s_rowm[128], s_rowl[128], s_rowlab[128];
    __shared__ int   s_lab[128];

    const int tid  = threadIdx.x;
    const int lane = tid & 31;
    const int warp = tid >> 5;
    const int wm   = warp & 3;
    const int wn   = warp >> 2;
    const int m0   = blockIdx.x * 128;
    const uint32_t stg = smem_u32(dyns);

    for (int i = tid; i < 1024; i += 256) s_bias[i] = g_bias[i];
    if (tid < 128) {
        int gr  = m0 + tid;
        int lab = (gr < N_ROWS) ? g_lab[gr]
                : (gr < M_TOTAL) ? (gr - N_ROWS) % C_CLS : -1;
        s_lab[tid]    = lab;
        s_rowm[tid]   = -1e30f;
        s_rowl[tid]   = 0.f;
        s_rowlab[tid] = 0.f;
    }

    uint32_t p_off[4];
    int      p_src[4];
#pragma unroll
    for (int i = 0; i < 4; ++i) {
        int q   = tid + i * 256;     // 0..1023
        int row = q >> 3, seg = q & 7;
        p_off[i] = (uint32_t)(row * 128 + ((seg * 16) ^ ((row & 7) << 4)));
        p_src[i] = row * A_DIM + seg * 8;
    }
    const __nv_bfloat16* arow = g_feats + (size_t)m0 * A_DIM;

    auto issue = [&](int g, int s) {
        int nt = g >> 4, kt = g & 15;
        uint32_t ab = stg + (uint32_t)s * STAGE_BYTES;
        const __nv_bfloat16* asrc = arow + kt * 64;
        const __nv_bfloat16* bsrc = g_w + (size_t)(nt << 7) * A_DIM + kt * 64;
#pragma unroll
        for (int i = 0; i < 4; ++i) {
            CP_ASYNC16(ab + p_off[i],         asrc + p_src[i]);
            CP_ASYNC16(ab + 16384 + p_off[i], bsrc + p_src[i]);
        }
        CP_COMMIT();
    };

    const int      arow0  = wm * 32 + (lane & 15);
    const int      brow0  = wn * 64 + (lane & 15);
    const uint32_t coloff = (uint32_t)((lane >> 4) * 16);
    const uint32_t swm    = (uint32_t)((lane & 7) << 4);

    issue(0, 0);
    issue(1, 1);

    float acc[2][8][4];
    int sC = 0, sI = 2;

    for (int g = 0; g < 128; ++g) {
        CP_WAIT1();
        __syncthreads();
        if (g + 2 < 128) {
            issue(g + 2, sI);
            if (++sI == STAGES) sI = 0;
        }
        if ((g & 15) == 0) {
#pragma unroll
            for (int mm = 0; mm < 2; ++mm)
#pragma unroll
                for (int nn = 0; nn < 8; ++nn)
#pragma unroll
                    for (int j = 0; j < 4; ++j) acc[mm][nn][j] = 0.f;
        }
        const uint32_t ab = stg + (uint32_t)sC * STAGE_BYTES;
        const uint32_t bb = ab + 16384;
        if (++sC == STAGES) sC = 0;
#pragma unroll
        for (int ks = 0; ks < 4; ++ks) {
            const uint32_t colb = (uint32_t)(ks * 32) + coloff;
            uint32_t a0[4], a1[4];
            LDSM4(a0[0], a0[1], a0[2], a0[3],
                  ab + (uint32_t)(arow0 * 128) + (colb ^ swm));
            LDSM4(a1[0], a1[1], a1[2], a1[3],
                  ab + (uint32_t)((arow0 + 16) * 128) + (colb ^ swm));
#pragma unroll
            for (int p = 0; p < 4; ++p) {
                uint32_t b[4];
                LDSM4(b[0], b[1], b[2], b[3],
                      bb + (uint32_t)((brow0 + p * 16) * 128) + (colb ^ swm));
                MMA(acc[0][2 * p],     a0, b[0], b[2]);
                MMA(acc[0][2 * p + 1], a0, b[1], b[3]);
                MMA(acc[1][2 * p],     a1, b[0], b[2]);
                MMA(acc[1][2 * p + 1], a1, b[1], b[3]);
            }
        }

        if ((g & 15) == 15) {
            const int n0 = (g >> 4) * 128;
#pragma unroll
            for (int mm = 0; mm < 2; ++mm)
#pragma unroll
                for (int nn = 0; nn < 8; ++nn) {
                    int colb = n0 + wn * 64 + nn * 8 + (lane & 3) * 2;
                    acc[mm][nn][0] += s_bias[colb];
                    acc[mm][nn][1] += s_bias[colb + 1];
                    acc[mm][nn][2] += s_bias[colb];
                    acc[mm][nn][3] += s_bias[colb + 1];
                }
#pragma unroll
            for (int mm = 0; mm < 2; ++mm)
#pragma unroll
                for (int half = 0; half < 2; ++half) {
                    float tm = -1e30f;
#pragma unroll
                    for (int nn = 0; nn < 8; ++nn) {
                        tm = fmaxf(tm, acc[mm][nn][half * 2]);
                        tm = fmaxf(tm, acc[mm][nn][half * 2 + 1]);
                    }
                    tm = fmaxf(tm, __shfl_xor_sync(0xffffffffu, tm, 1));
                    tm = fmaxf(tm, __shfl_xor_sync(0xffffffffu, tm, 2));
                    if ((lane & 3) == 0)
                        s_redm[wn][wm * 32 + mm * 16 + half * 8 + (lane >> 2)] = tm;
                }
            __syncthreads();
#pragma unroll
            for (int mm = 0; mm < 2; ++mm)
#pragma unroll
                for (int half = 0; half < 2; ++half) {
                    int   row  = wm * 32 + mm * 16 + half * 8 + (lane >> 2);
                    float mnew = fmaxf(s_rowm[row], fmaxf(s_redm[0][row], s_redm[1][row]));
                    int   lab  = s_lab[row];
                    float se   = 0.f;
#pragma unroll
                    for (int nn = 0; nn < 8; ++nn)
#pragma unroll
                        for (int i = 0; i < 2; ++i) {
                            float v = acc[mm][nn][half * 2 + i];
                            se += __expf(v - mnew);
                            int gcol = n0 + wn * 64 + nn * 8 + (lane & 3) * 2 + i;
                            if (gcol == lab) s_rowlab[row] = v;
                        }
                    se += __shfl_xor_sync(0xffffffffu, se, 1);
                    se += __shfl_xor_sync(0xffffffffu, se, 2);
                    if ((lane & 3) == 0) s_redl[wn][row] = se;
                }
            __syncthreads();
            if (tid < 128) {
                float mold = s_rowm[tid];
                float mnew = fmaxf(mold, fmaxf(s_redm[0][tid], s_redm[1][tid]));
                s_rowl[tid] = s_rowl[tid] * __expf(mold - mnew)
                            + s_redl[0][tid] + s_redl[1][tid];
                s_rowm[tid] = mnew;
            }
            __syncthreads();
        }
    }

    if (tid < 128) {
        int   gr = m0 + tid;
        float c  = 0.f;
        if (gr < M_TOTAL)
            c = s_rowm[tid] + logf(s_rowl[tid]) - s_rowlab[tid];
#pragma unroll
        for (int o = 16; o; o >>= 1) c += __shfl_xor_sync(0xffffffffu, c, o);
        if (lane == 0) atomicAdd(&g_loss, c);
    }
}

__global__ void k_final(float* out) {
    out[0] = g_loss / (float)M_TOTAL;
}

// ---------------- launch ----------------
extern "C" void kernel_launch(void* const* d_in, const int* in_sizes, int n_in,
                              void* d_out, int out_size) {
    const float* x            = (const float*)d_in[0];
    const float* eps          = (const float*)d_in[1];
    const float* fc_w         = (const float*)d_in[2];
    const float* fc_b         = (const float*)d_in[3];
    const float* ba           = (const float*)d_in[4];
    const float* cov_prior    = (const float*)d_in[5];
    const float* ave_prior    = (const float*)d_in[6];
    const float* amount_prior = (const float*)d_in[7];
    const int*   labels_raw   = (const int*)d_in[8];

    cudaFuncSetAttribute(k_gemm_loss,
                         cudaFuncAttributeMaxDynamicSharedMemorySize, SMEM_DYN);

    k_pre<<<1156, 256>>>(labels_raw, fc_w);                          // #0
    k_labels_count<<<256, 256>>>(labels_raw);                        // #1
    k_scan_bias<<<2, 1024>>>(fc_b, ba);                              // #2
    k_scatter_pad<<<448, 256>>>();                                   // #3
    k_stats<<<C_CLS, 256>>>(x, eps, cov_prior, ave_prior, amount_prior); // #4
    k_gemm_loss<<<M_TILES, 256, SMEM_DYN>>>();                       // #5
    k_final<<<1, 1>>>((float*)d_out);                                // #6
}

// round 16
// speedup vs baseline: 1.0617x; 1.0074x over previous
#include <cuda_runtime.h>
#include <cuda_bf16.h>
#include <cstdint>
#include <cstddef>

#define N_ROWS   65536
#define A_DIM    1024
#define C_CLS    1000
#define S_AUG    2
#define M_TOTAL  (N_ROWS + S_AUG * C_CLS)   /* 67536 */
#define M_TILES  528
#define M_PAD    (M_TILES * 128)            /* 67584 */
#define NPAD     1024
#define STAGES   3
#define STAGE_BYTES 32768                   /* A 16KB + B 16KB */
#define SMEM_DYN (STAGES * STAGE_BYTES)     /* 98304 */

// ---------------- persistent device scratch ----------------
__device__ int   g_cnt[C_CLS];
__device__ int   g_off[C_CLS];
__device__ int   g_wptr[C_CLS];
__device__ int   g_idx[N_ROWS];
__device__ int   g_lab[N_ROWS];
__device__ int   g_blockor[8];
__device__ int   g_done;
__device__ float g_loss;
__device__ __nv_bfloat16 g_feats[(size_t)M_PAD * A_DIM];   // [x ; aug ; zero-pad] bf16
__device__ __nv_bfloat16 g_w[(size_t)NPAD * A_DIM];        // fc_w padded, bf16
__device__ float g_bias[NPAD];                             // fc_b - ba, pad = -1e30

// ============ PTX helpers ============
__device__ __forceinline__ uint32_t smem_u32(const void* p) {
    uint32_t a;
    asm("{ .reg .u64 t; cvta.to.shared.u64 t, %1; cvt.u32.u64 %0, t; }" : "=r"(a) : "l"(p));
    return a;
}
#define CP_ASYNC16(dst, src) \
    asm volatile("cp.async.cg.shared.global [%0], [%1], 16;" :: "r"(dst), "l"(src) : "memory")
#define CP_COMMIT() asm volatile("cp.async.commit_group;" ::: "memory")
#define CP_WAIT1()  asm volatile("cp.async.wait_group 1;" ::: "memory")
#define LDSM4(r0, r1, r2, r3, a) \
    asm volatile("ldmatrix.sync.aligned.m8n8.x4.shared.b16 {%0,%1,%2,%3}, [%4];" \
                 : "=r"(r0), "=r"(r1), "=r"(r2), "=r"(r3) : "r"(a))
#define MMA(acc, a, b0, b1) \
    asm volatile("mma.sync.aligned.m16n8k16.row.col.f32.bf16.bf16.f32 " \
                 "{%0,%1,%2,%3},{%4,%5,%6,%7},{%8,%9},{%0,%1,%2,%3};" \
                 : "+f"((acc)[0]), "+f"((acc)[1]), "+f"((acc)[2]), "+f"((acc)[3]) \
                 : "r"((a)[0]), "r"((a)[1]), "r"((a)[2]), "r"((a)[3]), \
                   "r"(b0), "r"(b1))

// ---------------- #0: fused convw + int64-detect(sampled) + counter init ----------------
__global__ void k_pre(const int* __restrict__ raw, const float* __restrict__ fc_w) {
    int b   = blockIdx.x;
    int tid = threadIdx.x;
    if (b < 1024) {
        int idx = b * 256 + tid;                 // 4 floats each
        __nv_bfloat162 lo, hi;
        if (idx < (C_CLS * A_DIM) / 4) {
            float4 v = reinterpret_cast<const float4*>(fc_w)[idx];
            lo = __floats2bfloat162_rn(v.x, v.y);
            hi = __floats2bfloat162_rn(v.z, v.w);
        } else {
            lo = __floats2bfloat162_rn(0.f, 0.f); hi = lo;
        }
        reinterpret_cast<__nv_bfloat162*>(g_w)[(size_t)idx * 2]     = lo;
        reinterpret_cast<__nv_bfloat162*>(g_w)[(size_t)idx * 2 + 1] = hi;
    } else if (b < 1032) {
        int d = b - 1024;
        int i = d * 256 + tid;                   // sample first 2048 odd 32-bit words
        int nz = (raw[2 * i + 1] != 0) ? 1 : 0;
        int any = __syncthreads_or(nz);
        if (tid == 0) g_blockor[d] = any;        // overwrite: no reset needed
    } else {
        int i = (b - 1032) * 256 + tid;
        if (i < C_CLS) { g_cnt[i] = 0; g_wptr[i] = 0; }
        if (i == 0) { g_loss = 0.f; g_done = 0; }
    }
}

// ---------------- #1: labels (int64/int32 auto) + histogram ----------------
__global__ void k_labels_count(const int* __restrict__ raw) {
    int tid = threadIdx.x;
    int v   = (tid < 8) ? g_blockor[tid] : 0;
    int any = __syncthreads_or(v);               // any odd word nonzero => int32 buffer
    int i   = blockIdx.x * blockDim.x + tid;
    if (i < N_ROWS) {
        int lab = any ? raw[i] : raw[2 * i];
        g_lab[i] = lab;
        atomicAdd(&g_cnt[lab], 1);
    }
}

// ---------------- #2: scan (block0) + bias (block1) ----------------
__global__ void k_scan_bias(const float* __restrict__ fc_b, const float* __restrict__ ba) {
    int tid = threadIdx.x;
    if (blockIdx.x == 1) {
        g_bias[tid] = (tid < C_CLS) ? (fc_b[tid] - ba[tid]) : -1e30f;
        return;
    }
    __shared__ int sa[1024], sb[1024];
    int v = (tid < C_CLS) ? g_cnt[tid] : 0;
    sa[tid] = v; __syncthreads();
    int* src = sa; int* dst = sb;
    for (int o = 1; o < 1024; o <<= 1) {
        int t = src[tid];
        if (tid >= o) t += src[tid - o];
        dst[tid] = t; __syncthreads();
        int* tmp = src; src = dst; dst = tmp;
    }
    if (tid < C_CLS) g_off[tid] = src[tid] - v;
}

// ---------------- #3: scatter (blocks<256) + zero-pad tail rows ----------------
__global__ void k_scatter_pad() {
    int b   = blockIdx.x;
    int tid = threadIdx.x;
    if (b < 256) {
        int i = b * 256 + tid;
        int lab = g_lab[i];
        int pos = atomicAdd(&g_wptr[lab], 1);
        g_idx[g_off[lab] + pos] = i;
    } else {
        int j = (b - 256) * 256 + tid;
        if (j < (M_PAD - M_TOTAL) * A_DIM)
            g_feats[(size_t)M_TOTAL * A_DIM + j] = __float2bfloat16(0.f);
    }
}

// ---------------- #4: per-class stats + aug build + x->bf16 (gather via g_idx) ----------------
__global__ void k_stats(const float* __restrict__ x,
                        const float* __restrict__ eps,
                        const float* __restrict__ cov_prior,
                        const float* __restrict__ ave_prior,
                        const float* __restrict__ amount_prior) {
    int c   = blockIdx.x;
    int tid = threadIdx.x;            // thread owns 4 contiguous cols
    int cnt = g_cnt[c];
    int off = g_off[c];
    float sum[4] = {0, 0, 0, 0}, sq[4] = {0, 0, 0, 0};
#pragma unroll 2
    for (int j = 0; j < cnt; ++j) {
        int r = g_idx[off + j];
        float4 v = *reinterpret_cast<const float4*>(x + (size_t)r * A_DIM + tid * 4);
        __nv_bfloat162 lo = __floats2bfloat162_rn(v.x, v.y);
        __nv_bfloat162 hi = __floats2bfloat162_rn(v.z, v.w);
        uint2 pk;
        pk.x = *reinterpret_cast<uint32_t*>(&lo);
        pk.y = *reinterpret_cast<uint32_t*>(&hi);
        *reinterpret_cast<uint2*>(&g_feats[(size_t)r * A_DIM + tid * 4]) = pk;
        sum[0] += v.x; sq[0] += v.x * v.x;
        sum[1] += v.y; sq[1] += v.y * v.y;
        sum[2] += v.z; sq[2] += v.z * v.z;
        sum[3] += v.w; sq[3] += v.w * v.w;
    }
    float cntf  = (float)cnt;
    float cnt_c = (cnt == 0) ? 1.f : cntf;
    float w     = cntf / (cntf + amount_prior[c] + 1e-10f);
#pragma unroll
    for (int t = 0; t < 4; ++t) {
        int a = tid * 4 + t;
        float ave = sum[t] / cnt_c;
        float var = sq[t] / cnt_c - ave * ave;
        var = fmaxf(var, 0.f);
        if (var == 0.f) var = 1e-10f;
        float ap   = ave_prior[(size_t)c * A_DIM + a];
        float addl = w * (1.f - w) * (ap - ave) * (ap - ave);
        float ncov = cov_prior[(size_t)c * A_DIM + a] * (1.f - w) + var * w + addl;
        float nave = ap * (1.f - w) + ave * w;
#pragma unroll
        for (int s = 0; s < S_AUG; ++s) {
            float e = eps[((size_t)s * C_CLS + c) * A_DIM + a];
            g_feats[(size_t)(N_ROWS + s * C_CLS + c) * A_DIM + a] =
                __float2bfloat16(nave + ncov * e);
        }
    }
}

// ---------------- #5: champion GEMM (128x128, 256 thr, occ 2) + fused final ----------------
__global__ void __launch_bounds__(256, 2) k_gemm_loss(float* __restrict__ out) {
    extern __shared__ __align__(1024) char dyns[];   // STAGES x (A 16KB | B 16KB)
    __shared__ float s_bias[1024];
    __shared__ float s_redm[2][128], s_redl[2][128];
    __shared__ float s_rowm[128], s_rowl[128], s_rowlab[128];
    __shared__ int   s_lab[128];

    const int tid  = threadIdx.x;
    const int lane = tid & 31;
    const int warp = tid >> 5;
    const int wm   = warp & 3;
    const int wn   = warp >> 2;
    const int m0   = blockIdx.x * 128;
    const uint32_t stg = smem_u32(dyns);

    for (int i = tid; i < 1024; i += 256) s_bias[i] = g_bias[i];
    if (tid < 128) {
        int gr  = m0 + tid;
        int lab = (gr < N_ROWS) ? g_lab[gr]
                : (gr < M_TOTAL) ? (gr - N_ROWS) % C_CLS : -1;
        s_lab[tid]    = lab;
        s_rowm[tid]   = -1e30f;
        s_rowl[tid]   = 0.f;
        s_rowlab[tid] = 0.f;
    }

    uint32_t p_off[4];
    int      p_src[4];
#pragma unroll
    for (int i = 0; i < 4; ++i) {
        int q   = tid + i * 256;     // 0..1023
        int row = q >> 3, seg = q & 7;
        p_off[i] = (uint32_t)(row * 128 + ((seg * 16) ^ ((row & 7) << 4)));
        p_src[i] = row * A_DIM + seg * 8;
    }
    const __nv_bfloat16* arow = g_feats + (size_t)m0 * A_DIM;

    auto issue = [&](int g, int s) {
        int nt = g >> 4, kt = g & 15;
        uint32_t ab = stg + (uint32_t)s * STAGE_BYTES;
        const __nv_bfloat16* asrc = arow + kt * 64;
        const __nv_bfloat16* bsrc = g_w + (size_t)(nt << 7) * A_DIM + kt * 64;
#pragma unroll
        for (int i = 0; i < 4; ++i) {
            CP_ASYNC16(ab + p_off[i],         asrc + p_src[i]);
            CP_ASYNC16(ab + 16384 + p_off[i], bsrc + p_src[i]);
        }
        CP_COMMIT();
    };

    const int      arow0  = wm * 32 + (lane & 15);
    const int      brow0  = wn * 64 + (lane & 15);
    const uint32_t coloff = (uint32_t)((lane >> 4) * 16);
    const uint32_t swm    = (uint32_t)((lane & 7) << 4);

    issue(0, 0);
    issue(1, 1);

    float acc[2][8][4];
    int sC = 0, sI = 2;

    for (int g = 0; g < 128; ++g) {
        CP_WAIT1();
        __syncthreads();
        if (g + 2 < 128) {
            issue(g + 2, sI);
            if (++sI == STAGES) sI = 0;
        }
        if ((g & 15) == 0) {
#pragma unroll
            for (int mm = 0; mm < 2; ++mm)
#pragma unroll
                for (int nn = 0; nn < 8; ++nn)
#pragma unroll
                    for (int j = 0; j < 4; ++j) acc[mm][nn][j] = 0.f;
        }
        const uint32_t ab = stg + (uint32_t)sC * STAGE_BYTES;
        const uint32_t bb = ab + 16384;
        if (++sC == STAGES) sC = 0;
#pragma unroll
        for (int ks = 0; ks < 4; ++ks) {
            const uint32_t colb = (uint32_t)(ks * 32) + coloff;
            uint32_t a0[4], a1[4];
            LDSM4(a0[0], a0[1], a0[2], a0[3],
                  ab + (uint32_t)(arow0 * 128) + (colb ^ swm));
            LDSM4(a1[0], a1[1], a1[2], a1[3],
                  ab + (uint32_t)((arow0 + 16) * 128) + (colb ^ swm));
#pragma unroll
            for (int p = 0; p < 4; ++p) {
                uint32_t b[4];
                LDSM4(b[0], b[1], b[2], b[3],
                      bb + (uint32_t)((brow0 + p * 16) * 128) + (colb ^ swm));
                MMA(acc[0][2 * p],     a0, b[0], b[2]);
                MMA(acc[0][2 * p + 1], a0, b[1], b[3]);
                MMA(acc[1][2 * p],     a1, b[0], b[2]);
                MMA(acc[1][2 * p + 1], a1, b[1], b[3]);
            }
        }

        if ((g & 15) == 15) {
            const int n0 = (g >> 4) * 128;
#pragma unroll
            for (int mm = 0; mm < 2; ++mm)
#pragma unroll
                for (int nn = 0; nn < 8; ++nn) {
                    int colb = n0 + wn * 64 + nn * 8 + (lane & 3) * 2;
                    acc[mm][nn][0] += s_bias[colb];
                    acc[mm][nn][1] += s_bias[colb + 1];
                    acc[mm][nn][2] += s_bias[colb];
                    acc[mm][nn][3] += s_bias[colb + 1];
                }
#pragma unroll
            for (int mm = 0; mm < 2; ++mm)
#pragma unroll
                for (int half = 0; half < 2; ++half) {
                    float tm = -1e30f;
#pragma unroll
                    for (int nn = 0; nn < 8; ++nn) {
                        tm = fmaxf(tm, acc[mm][nn][half * 2]);
                        tm = fmaxf(tm, acc[mm][nn][half * 2 + 1]);
                    }
                    tm = fmaxf(tm, __shfl_xor_sync(0xffffffffu, tm, 1));
                    tm = fmaxf(tm, __shfl_xor_sync(0xffffffffu, tm, 2));
                    if ((lane & 3) == 0)
                        s_redm[wn][wm * 32 + mm * 16 + half * 8 + (lane >> 2)] = tm;
                }
            __syncthreads();
#pragma unroll
            for (int mm = 0; mm < 2; ++mm)
#pragma unroll
                for (int half = 0; half < 2; ++half) {
                    int   row  = wm * 32 + mm * 16 + half * 8 + (lane >> 2);
                    float mnew = fmaxf(s_rowm[row], fmaxf(s_redm[0][row], s_redm[1][row]));
                    int   lab  = s_lab[row];
                    float se   = 0.f;
#pragma unroll
                    for (int nn = 0; nn < 8; ++nn)
#pragma unroll
                        for (int i = 0; i < 2; ++i) {
                            float v = acc[mm][nn][half * 2 + i];
                            se += __expf(v - mnew);
                            int gcol = n0 + wn * 64 + nn * 8 + (lane & 3) * 2 + i;
                            if (gcol == lab) s_rowlab[row] = v;
                        }
                    se += __shfl_xor_sync(0xffffffffu, se, 1);
                    se += __shfl_xor_sync(0xffffffffu, se, 2);
                    if ((lane & 3) == 0) s_redl[wn][row] = se;
                }
            __syncthreads();
            if (tid < 128) {
                float mold = s_rowm[tid];
                float mnew = fmaxf(mold, fmaxf(s_redm[0][tid], s_redm[1][tid]));
                s_rowl[tid] = s_rowl[tid] * __expf(mold - mnew)
                            + s_redl[0][tid] + s_redl[1][tid];
                s_rowm[tid] = mnew;
            }
            __syncthreads();
        }
    }

    // ---- per-row loss, block reduce, device accumulate + fused final write ----
    if (tid < 128) {
        int   gr = m0 + tid;
        float c  = 0.f;
        if (gr < M_TOTAL)
            c = s_rowm[tid] + logf(s_rowl[tid]) - s_rowlab[tid];
#pragma unroll
        for (int o = 16; o; o >>= 1) c += __shfl_xor_sync(0xffffffffu, c, o);
        if (lane == 0) {
            atomicAdd(&g_loss, c);
            __threadfence();              // order loss atomic before done-count
        }
    }
    __syncthreads();
    if (tid == 0) {
        int done = atomicAdd(&g_done, 1);
        if (done == M_TILES - 1) {
            float total = atomicAdd(&g_loss, 0.f);   // coherent read of final sum
            out[0] = total / (float)M_TOTAL;
        }
    }
}

// ---------------- launch ----------------
extern "C" void kernel_launch(void* const* d_in, const int* in_sizes, int n_in,
                              void* d_out, int out_size) {
    const float* x            = (const float*)d_in[0];
    const float* eps          = (const float*)d_in[1];
    const float* fc_w         = (const float*)d_in[2];
    const float* fc_b         = (const float*)d_in[3];
    const float* ba           = (const float*)d_in[4];
    const float* cov_prior    = (const float*)d_in[5];
    const float* ave_prior    = (const float*)d_in[6];
    const float* amount_prior = (const float*)d_in[7];
    const int*   labels_raw   = (const int*)d_in[8];

    cudaFuncSetAttribute(k_gemm_loss,
                         cudaFuncAttributeMaxDynamicSharedMemorySize, SMEM_DYN);

    k_pre<<<1036, 256>>>(labels_raw, fc_w);                          // #0
    k_labels_count<<<256, 256>>>(labels_raw);                        // #1
    k_scan_bias<<<2, 1024>>>(fc_b, ba);                              // #2
    k_scatter_pad<<<448, 256>>>();                                   // #3
    k_stats<<<C_CLS, 256>>>(x, eps, cov_prior, ave_prior, amount_prior); // #4
    k_gemm_loss<<<M_TILES, 256, SMEM_DYN>>>((float*)d_out);          // #5
}